// round 16
// baseline (speedup 1.0000x reference)
#include <cuda_runtime.h>
#include <cuda_bf16.h>

// ---------------------------------------------------------------------------
// MultiLayerGnn: 3-layer GCN (+linear skips) + global_sort_pool top-K
// N=50000, E=800000, F_IN=H=64, C_OUT=32, K=1024
// r15 (deterministic eid-ordered CSR, row-chunk pipeline, double-buffered hw)
// with: sort_rows in LOCAL memory + fused norm finalize -> agg kernels use
// proven {src, norm} records (1 load/edge). Agg math bit-identical to r15.
// ---------------------------------------------------------------------------

#define NMAX 50000
#define EMAX 800000
#define KTOP 1024
#define MAXDEG_LOCAL 96

static constexpr size_t AL(size_t x) { return (x + 255) & ~size_t(255); }

static constexpr size_t OFF_HW1  = 0;
static constexpr size_t OFF_HW2  = AL(OFF_HW1  + (size_t)NMAX * 64 * 4);
static constexpr size_t OFF_ACCA = AL(OFF_HW2  + (size_t)NMAX * 64 * 4);
static constexpr size_t OFF_ACCB = AL(OFF_ACCA + (size_t)NMAX * 64 * 4);
static constexpr size_t OFF_DINV = AL(OFF_ACCB + (size_t)NMAX * 64 * 4);
static constexpr size_t OFF_DEG  = AL(OFF_DINV + (size_t)NMAX * 4);
static constexpr size_t OFF_FILL = AL(OFF_DEG  + (size_t)NMAX * 4);
static constexpr size_t OFF_RP   = AL(OFF_FILL + (size_t)NMAX * 4);
static constexpr size_t OFF_EDG  = AL(OFF_RP   + (size_t)(NMAX + 1) * 4);
static constexpr size_t OFF_SKEY = AL(OFF_EDG  + (size_t)EMAX * 8);
static constexpr size_t OFF_H1   = AL(OFF_SKEY + (size_t)NMAX * 4);
static constexpr size_t OFF_BSUM = AL(OFF_H1   + 4096 * 4);
static constexpr size_t SCRATCH_TOTAL = AL(OFF_BSUM + 256 * 4);

__device__ __align__(256) unsigned char g_scratch[SCRATCH_TOTAL];

// ---------------------------------------------------------------------------
// f32x2 packed-FMA helpers (bit-identical per-lane to fmaf)
// ---------------------------------------------------------------------------

#define FMA2(d, a, b, c) \
    asm("fma.rn.f32x2 %0, %1, %2, %3;" : "=l"(d) : "l"(a), "l"(b), "l"(c))

__device__ __forceinline__ unsigned long long dup2(float x) {
    unsigned long long r; unsigned u = __float_as_uint(x);
    asm("mov.b64 %0, {%1, %2};" : "=l"(r) : "r"(u), "r"(u));
    return r;
}

__device__ __forceinline__ float2 unpk2(unsigned long long v) {
    unsigned lo, hi;
    asm("mov.b64 {%0, %1}, %2;" : "=r"(lo), "=r"(hi) : "l"(v));
    return make_float2(__uint_as_float(lo), __uint_as_float(hi));
}

// ---------------------------------------------------------------------------
// Prep kernels (deg = edge-only count; self-loop via d+1)
// ---------------------------------------------------------------------------

__global__ void init_kernel(int* deg, int* fill, int* hist1, int n) {
    int i = blockIdx.x * blockDim.x + threadIdx.x;
    if (i < n) { deg[i] = 0; fill[i] = 0; }
    if (i < 4096) hist1[i] = 0;
}

// 4 edges per thread for atomic MLP.
__global__ void deg_kernel(const int* __restrict__ ei, int e,
                           int* __restrict__ deg, int n) {
    int i = (blockIdx.x * blockDim.x + threadIdx.x) * 4;
#pragma unroll
    for (int k = 0; k < 4; k++) {
        int j = i + k;
        if (j < e) {
            unsigned d = (unsigned)ei[e + j];
            if (d < (unsigned)n) atomicAdd(&deg[d], 1);
        }
    }
}

__global__ void scanA(const int* __restrict__ deg, float* __restrict__ dinv,
                      int* __restrict__ bsum, int n) {
    __shared__ int sh[256];
    int t = threadIdx.x;
    int i = blockIdx.x * 256 + t;
    int v = 0;
    if (i < n) {
        int d = deg[i];
        dinv[i] = rsqrtf((float)(d + 1));
        v = d;
    }
    sh[t] = v;
    __syncthreads();
    for (int off = 128; off > 0; off >>= 1) {
        if (t < off) sh[t] += sh[t + off];
        __syncthreads();
    }
    if (t == 0) bsum[blockIdx.x] = sh[0];
}

__global__ void scanC2(const int* __restrict__ deg, const int* __restrict__ bsum,
                       int* __restrict__ rowptr, int nb, int n) {
    __shared__ int sh[256];
    __shared__ int pref;
    int t = threadIdx.x, bid = blockIdx.x;
    sh[t] = (t < bid) ? bsum[t] : 0;     // nb <= 256
    __syncthreads();
    for (int off = 128; off > 0; off >>= 1) {
        if (t < off) sh[t] += sh[t + off];
        __syncthreads();
    }
    if (t == 0) pref = sh[0];
    __syncthreads();
    int i = bid * 256 + t;
    int v = (i < n) ? deg[i] : 0;
    sh[t] = v;
    __syncthreads();
    for (int off = 1; off < 256; off <<= 1) {
        int x = (t >= off) ? sh[t - off] : 0;
        __syncthreads();
        sh[t] += x;
        __syncthreads();
    }
    if (i < n) rowptr[i] = pref + sh[t] - v;
    if (bid == nb - 1 && t == 0) rowptr[n] = pref + bsum[bid];
}

// Records {src, eid}; slot order nondeterministic (atomic), canonicalized by
// sort_rows (eid unique -> unique total order = original edge order).
__global__ void scatter_kernel(const int* __restrict__ ei, int e,
                               const int* __restrict__ rowptr,
                               int* __restrict__ fill,
                               int2* __restrict__ edges, int n) {
    int i = (blockIdx.x * blockDim.x + threadIdx.x) * 4;
#pragma unroll
    for (int k = 0; k < 4; k++) {
        int j = i + k;
        if (j < e) {
            unsigned s = (unsigned)ei[j];
            unsigned d = (unsigned)ei[e + j];
            if (s < (unsigned)n && d < (unsigned)n) {
                int p = atomicAdd(&fill[d], 1);
                edges[rowptr[d] + p] = make_int2((int)s, j);
            }
        }
    }
}

// Sort each row by eid (unique -> canonical original-edge order), then
// rewrite records as {src, norm} with norm = dinv[src]*dinv[node]
// (same operands/rounding as all prior versions -> bit-identical).
// Local-memory buffer keeps the serial sort chain in L1.
__global__ void sort_rows(int2* __restrict__ edges,
                          const int* __restrict__ rowptr,
                          const float* __restrict__ dinv, int n) {
    int w = blockIdx.x * blockDim.x + threadIdx.x;
    if (w >= n) return;
    int r0 = rowptr[w], r1 = rowptr[w + 1];
    int len = r1 - r0;
    float di = dinv[w];
    if (len <= MAXDEG_LOCAL) {
        int2 buf[MAXDEG_LOCAL];
        for (int i = 0; i < len; i++) buf[i] = edges[r0 + i];
        for (int i = 1; i < len; i++) {
            int2 key = buf[i];
            int j = i - 1;
            while (j >= 0 && buf[j].y > key.y) { buf[j + 1] = buf[j]; j--; }
            buf[j + 1] = key;
        }
        for (int i = 0; i < len; i++) {
            int s = buf[i].x;
            edges[r0 + i] = make_int2(s, __float_as_int(dinv[s] * di));
        }
    } else {
        for (int i = r0 + 1; i < r1; i++) {
            int2 key = edges[i];
            int j = i - 1;
            while (j >= r0 && edges[j].y > key.y) { edges[j + 1] = edges[j]; j--; }
            edges[j + 1] = key;
        }
        for (int i = r0; i < r1; i++) {
            int s = edges[i].x;
            edges[i] = make_int2(s, __float_as_int(dinv[s] * di));
        }
    }
}

// ---------------------------------------------------------------------------
// Fused GEMM via packed f32x2 FMA (r8 math, + row-chunk base r0)
// ---------------------------------------------------------------------------

template <int CW, bool SKIP>
__global__ __launch_bounds__(128) void gemm_fused(
    const float* __restrict__ hin,
    const float* __restrict__ W, const float* __restrict__ Wl,
    const float* __restrict__ b, const float* __restrict__ bl,
    float* __restrict__ hw, float* __restrict__ accout, int n, int r0) {
    constexpr int HOUT = SKIP ? CW / 2 : CW;
    constexpr int CT = CW / 16;
    constexpr int CT2 = CT / 2;
    __shared__ float As[64][64];   // As[k][row] (transposed)
    __shared__ float Ws[64][CW];

    int tid = threadIdx.x;
    int base = r0 + blockIdx.x * 64;

    for (int f = tid; f < 64 * 16; f += 128) {
        int row = f >> 4, c4 = f & 15;
        float4 v = make_float4(0.f, 0.f, 0.f, 0.f);
        int gr = base + row;
        if (gr < n) v = ((const float4*)hin)[(size_t)gr * 16 + c4];
        int k = c4 * 4;
        As[k + 0][row] = v.x;
        As[k + 1][row] = v.y;
        As[k + 2][row] = v.z;
        As[k + 3][row] = v.w;
    }
    for (int f = tid; f < 64 * CW; f += 128) {
        int k = f / CW, j = f % CW;
        float w;
        if (SKIP) w = (j < HOUT) ? W[k * HOUT + j] : Wl[k * HOUT + (j - HOUT)];
        else      w = W[k * CW + j];
        Ws[k][j] = w;
    }
    __syncthreads();

    int tcol = tid & 15, trow = tid >> 4;
    unsigned long long acc2[8][CT2];
#pragma unroll
    for (int i = 0; i < 8; i++)
#pragma unroll
        for (int c = 0; c < CT2; c++) acc2[i][c] = 0ull;

#pragma unroll 4
    for (int k = 0; k < 64; k++) {
        float4 a0 = *(const float4*)&As[k][trow * 8];
        float4 a1 = *(const float4*)&As[k][trow * 8 + 4];
        float a[8] = {a0.x, a0.y, a0.z, a0.w, a1.x, a1.y, a1.z, a1.w};
        unsigned long long w2[CT2];
#pragma unroll
        for (int c = 0; c < CT2; c++)
            w2[c] = *(const unsigned long long*)&Ws[k][tcol * CT + 2 * c];
#pragma unroll
        for (int i = 0; i < 8; i++) {
            unsigned long long ad = dup2(a[i]);
#pragma unroll
            for (int c = 0; c < CT2; c++)
                FMA2(acc2[i][c], ad, w2[c], acc2[i][c]);
        }
    }

#pragma unroll
    for (int i = 0; i < 8; i++) {
        int gr = base + trow * 8 + i;
        if (gr >= n) continue;
#pragma unroll
        for (int c = 0; c < CT2; c++) {
            int col = tcol * CT + 2 * c;
            float2 p = unpk2(acc2[i][c]);
            if (SKIP) {
                if (col < HOUT) {
                    *(float2*)&hw[(size_t)gr * HOUT + col] = p;
                } else {
                    int j = col - HOUT;
                    accout[(size_t)gr * HOUT + j]     = b[j]     + 0.5f * (p.x + bl[j]);
                    accout[(size_t)gr * HOUT + j + 1] = b[j + 1] + 0.5f * (p.y + bl[j + 1]);
                }
            } else {
                *(float2*)&hw[(size_t)gr * CW + col] = p;
            }
        }
    }
}

// ---------------------------------------------------------------------------
// Aggregation: warp per node over [w0, wend); {src, norm} records.
// ---------------------------------------------------------------------------

__global__ void agg64(const float* __restrict__ hw, const float* accin,
                      const float* __restrict__ dinv,
                      const int* __restrict__ rowptr,
                      const int2* __restrict__ edges,
                      float* out, int w0, int wend) {
    int w = w0 + ((blockIdx.x * blockDim.x + threadIdx.x) >> 5);
    int lane = threadIdx.x & 31;
    if (w >= wend) return;
    const float2* hp = (const float2*)hw;
    float di = dinv[w];
    float di2 = di * di;
    float2 s2 = hp[(size_t)w * 32 + lane];
    float ax = s2.x * di2, ay = s2.y * di2;
    int e = rowptr[w], e1 = rowptr[w + 1];
    for (; e + 3 < e1; e += 4) {
        int2 d0 = edges[e],     d1 = edges[e + 1];
        int2 d2 = edges[e + 2], d3 = edges[e + 3];
        float2 v0 = hp[(size_t)d0.x * 32 + lane];
        float2 v1 = hp[(size_t)d1.x * 32 + lane];
        float2 v2 = hp[(size_t)d2.x * 32 + lane];
        float2 v3 = hp[(size_t)d3.x * 32 + lane];
        float n0 = __int_as_float(d0.y), n1 = __int_as_float(d1.y);
        float n2 = __int_as_float(d2.y), n3 = __int_as_float(d3.y);
        ax = fmaf(v0.x, n0, ax); ay = fmaf(v0.y, n0, ay);
        ax = fmaf(v1.x, n1, ax); ay = fmaf(v1.y, n1, ay);
        ax = fmaf(v2.x, n2, ax); ay = fmaf(v2.y, n2, ay);
        ax = fmaf(v3.x, n3, ax); ay = fmaf(v3.y, n3, ay);
    }
    for (; e < e1; e++) {
        int2 d0 = edges[e];
        float2 va = hp[(size_t)d0.x * 32 + lane];
        float na = __int_as_float(d0.y);
        ax = fmaf(va.x, na, ax); ay = fmaf(va.y, na, ay);
    }
    float2 bse = ((const float2*)accin)[(size_t)w * 32 + lane];
    float rx = fmaxf(bse.x + ax, 0.f);
    float ry = fmaxf(bse.y + ay, 0.f);
    ((float2*)out)[(size_t)w * 32 + lane] = make_float2(rx, ry);
}

// Layer-3 agg (32 ch) + fused sort-key + hist1 (lane 31 owns channel 31).
__global__ void agg32_key(const float* __restrict__ hw, const float* __restrict__ bias,
                          const float* __restrict__ dinv,
                          const int* __restrict__ rowptr,
                          const int2* __restrict__ edges,
                          float* __restrict__ out, int w0, int wend,
                          unsigned* __restrict__ skey, int* __restrict__ hist1) {
    int w = w0 + ((blockIdx.x * blockDim.x + threadIdx.x) >> 5);
    int lane = threadIdx.x & 31;
    if (w >= wend) return;
    float di = dinv[w];
    float di2 = di * di;
    float acc = hw[(size_t)w * 32 + lane] * di2;
    int e = rowptr[w], e1 = rowptr[w + 1];
    for (; e + 3 < e1; e += 4) {
        int2 d0 = edges[e],     d1 = edges[e + 1];
        int2 d2 = edges[e + 2], d3 = edges[e + 3];
        float v0 = hw[(size_t)d0.x * 32 + lane];
        float v1 = hw[(size_t)d1.x * 32 + lane];
        float v2 = hw[(size_t)d2.x * 32 + lane];
        float v3 = hw[(size_t)d3.x * 32 + lane];
        acc = fmaf(v0, __int_as_float(d0.y), acc);
        acc = fmaf(v1, __int_as_float(d1.y), acc);
        acc = fmaf(v2, __int_as_float(d2.y), acc);
        acc = fmaf(v3, __int_as_float(d3.y), acc);
    }
    for (; e < e1; e++) {
        int2 d0 = edges[e];
        acc = fmaf(hw[(size_t)d0.x * 32 + lane], __int_as_float(d0.y), acc);
    }
    float v = acc + bias[lane];
    out[(size_t)w * 32 + lane] = v;
    if (lane == 31) {
        unsigned u = __float_as_uint(v);
        unsigned s = (u & 0x80000000u) ? ~u : (u | 0x80000000u);
        skey[w] = s;
        atomicAdd(&hist1[s >> 20], 1);
    }
}

// ---------------------------------------------------------------------------
// Merged top-K finisher (unchanged from r8)
// ---------------------------------------------------------------------------

__device__ __forceinline__ void findbin_warp(const int* __restrict__ hist,
                                             int base, int need,
                                             int* outB, int* outCum) {
    int lane = threadIdx.x & 31;
    int hi = 4095 - 128 * lane;
    int s = 0;
    for (int k = 0; k < 128; k++) s += hist[hi - k];
    int incl = s;
#pragma unroll
    for (int off = 1; off < 32; off <<= 1) {
        int x = __shfl_up_sync(0xFFFFFFFFu, incl, off);
        if (lane >= off) incl += x;
    }
    int excl = incl - s;
    if (base + excl < need && base + incl >= need) {
        int c = base + excl;
        int b = hi;
        while (c + hist[b] < need) { c += hist[b]; b--; }
        *outB = b;
        *outCum = c;
    }
}

__global__ __launch_bounds__(1024) void select_topk(
    const unsigned* __restrict__ skey, int n,
    const int* __restrict__ hist1,
    const float* __restrict__ h3, float* __restrict__ out) {
    __shared__ unsigned long long sd[4096];
    __shared__ int B1, C1, B2, C2, scnt;
    __shared__ unsigned Tsh;
    int* hist2 = (int*)sd;
    int tid = threadIdx.x;

    if (tid == 0) scnt = 0;
    for (int i = tid; i < 4096; i += 1024) hist2[i] = 0;
    __syncthreads();

    if (tid < 32) findbin_warp(hist1, 0, KTOP, &B1, &C1);
    __syncthreads();
    int b1 = B1, c1 = C1;

    for (int i = tid; i < n; i += 1024) {
        unsigned s = skey[i];
        if ((int)(s >> 20) == b1) atomicAdd(&hist2[(s >> 8) & 0xFFF], 1);
    }
    __syncthreads();

    if (tid < 32) findbin_warp(hist2, c1, KTOP, &B2, &C2);
    __syncthreads();
    if (tid == 0) Tsh = (((unsigned)b1) << 20) | (((unsigned)B2) << 8);
    __syncthreads();
    unsigned T = Tsh;
    __syncthreads();

    for (int i = tid; i < n; i += 1024) {
        unsigned s = skey[i];
        if (s >= T) {
            int p = atomicAdd(&scnt, 1);
            if (p < 4096)
                sd[p] = (((unsigned long long)s) << 32) |
                        (unsigned long long)(0xFFFFFFFFu - (unsigned)i);
        }
    }
    __syncthreads();

    int C = scnt; if (C > 4096) C = 4096;
    int S = 1024; while (S < C) S <<= 1;
    for (int i = tid; i < S; i += 1024) if (i >= C) sd[i] = 0ull;
    __syncthreads();
    for (int k = 2; k <= S; k <<= 1) {
        for (int j = k >> 1; j > 0; j >>= 1) {
            for (int t = tid; t < S; t += 1024) {
                int ixj = t ^ j;
                if (ixj > t) {
                    bool up = ((t & k) == 0);
                    unsigned long long A = sd[t], Bv = sd[ixj];
                    bool sw = up ? (A < Bv) : (A > Bv);
                    if (sw) { sd[t] = Bv; sd[ixj] = A; }
                }
            }
            __syncthreads();
        }
    }
    for (int t = tid; t < KTOP * 32; t += 1024) {
        int r = t >> 5, c = t & 31;
        unsigned idx = 0xFFFFFFFFu - (unsigned)(sd[r] & 0xFFFFFFFFull);
        out[t] = h3[(size_t)idx * 32 + c];
    }
}

// ---------------------------------------------------------------------------
// Launch: row-chunk pipelined across 2 streams, hw double-buffered.
// ---------------------------------------------------------------------------

extern "C" void kernel_launch(void* const* d_in, const int* in_sizes, int n_in,
                              void* d_out, int out_size) {
    const float* x   = (const float*)d_in[0];
    const float* W1  = (const float*)d_in[1];
    const float* b1  = (const float*)d_in[2];
    const float* Wl1 = (const float*)d_in[3];
    const float* bl1 = (const float*)d_in[4];
    const float* W2  = (const float*)d_in[5];
    const float* b2  = (const float*)d_in[6];
    const float* Wl2 = (const float*)d_in[7];
    const float* bl2 = (const float*)d_in[8];
    const float* W3  = (const float*)d_in[9];
    const float* b3  = (const float*)d_in[10];
    const int*   ei  = (const int*)d_in[11];

    int n = in_sizes[0] / 64;
    int e = in_sizes[11] / 2;

    unsigned char* base = nullptr;
    cudaGetSymbolAddress((void**)&base, g_scratch);

    float* hw1     = (float*)(base + OFF_HW1);
    float* hw2     = (float*)(base + OFF_HW2);
    float* accA    = (float*)(base + OFF_ACCA);
    float* accB    = (float*)(base + OFF_ACCB);
    float* dinv    = (float*)(base + OFF_DINV);
    int*   deg     = (int*)(base + OFF_DEG);
    int*   fill    = (int*)(base + OFF_FILL);
    int*   rowptr  = (int*)(base + OFF_RP);
    int2*  edges   = (int2*)(base + OFF_EDG);
    unsigned* skey = (unsigned*)(base + OFF_SKEY);
    int*   hist1   = (int*)(base + OFF_H1);
    int*   bsum    = (int*)(base + OFF_BSUM);

    int ninit = (n > 4096) ? n : 4096;
    int nb = (n + 255) / 256;

    int split = ((n / 2 + 63) / 64) * 64;
    if (split > n) split = n;
    int gA = split / 64;
    int gB = (n - split + 63) / 64;
    int aA = (split + 7) / 8;
    int aB = (n - split + 7) / 8;

    cudaStream_t s2;
    cudaStreamCreate(&s2);
    cudaEvent_t evFork, evG1, evA1a, evA1b, evG2, evA2a, evA2b, evG3, evA3;
    cudaEvent_t* evs[] = {&evFork, &evG1, &evA1a, &evA1b, &evG2, &evA2a,
                          &evA2b, &evG3, &evA3};
    for (auto ev : evs) cudaEventCreateWithFlags(ev, cudaEventDisableTiming);

    cudaEventRecord(evFork, 0);
    cudaStreamWaitEvent(s2, evFork, 0);

    // ---- prep branch (s2) ----
    init_kernel<<<(ninit + 255) / 256, 256, 0, s2>>>(deg, fill, hist1, n);
    deg_kernel<<<(e + 1023) / 1024, 256, 0, s2>>>(ei, e, deg, n);
    scanA<<<nb, 256, 0, s2>>>(deg, dinv, bsum, n);
    scanC2<<<nb, 256, 0, s2>>>(deg, bsum, rowptr, nb, n);
    scatter_kernel<<<(e + 1023) / 1024, 256, 0, s2>>>(ei, e, rowptr, fill, edges, n);
    sort_rows<<<(n + 255) / 256, 256, 0, s2>>>(edges, rowptr, dinv, n);

    // ---- layer 1 GEMM (main; independent of CSR) -> hw1 ----
    gemm_fused<128, true><<<gA + gB, 128>>>(x, W1, Wl1, b1, bl1, hw1, accA, n, 0);
    cudaEventRecord(evG1, 0);

    // ---- layer 1 aggs (s2; reads hw1) ----
    cudaStreamWaitEvent(s2, evG1, 0);
    agg64<<<aA, 256, 0, s2>>>(hw1, accA, dinv, rowptr, edges, accA, 0, split);
    cudaEventRecord(evA1a, s2);
    agg64<<<aB, 256, 0, s2>>>(hw1, accA, dinv, rowptr, edges, accA, split, n);
    cudaEventRecord(evA1b, s2);

    // ---- layer 2 GEMM chunks (main) -> hw2 (no conflict with agg1b on hw1) ----
    cudaStreamWaitEvent(0, evA1a, 0);
    gemm_fused<128, true><<<gA, 128>>>(accA, W2, Wl2, b2, bl2, hw2, accB, n, 0);
    cudaStreamWaitEvent(0, evA1b, 0);
    gemm_fused<128, true><<<gB, 128>>>(accA, W2, Wl2, b2, bl2, hw2, accB, n, split);
    cudaEventRecord(evG2, 0);

    // ---- layer 2 aggs (s2; reads hw2, full table) ----
    cudaStreamWaitEvent(s2, evG2, 0);
    agg64<<<aA, 256, 0, s2>>>(hw2, accB, dinv, rowptr, edges, accB, 0, split);
    cudaEventRecord(evA2a, s2);
    agg64<<<aB, 256, 0, s2>>>(hw2, accB, dinv, rowptr, edges, accB, split, n);
    cudaEventRecord(evA2b, s2);

    // ---- layer 3 GEMM chunks (main) -> hw1 (agg1 done with it long ago) ----
    cudaStreamWaitEvent(0, evA2a, 0);
    gemm_fused<32, false><<<gA, 128>>>(accB, W3, nullptr, nullptr, nullptr, hw1, nullptr, n, 0);
    cudaStreamWaitEvent(0, evA2b, 0);
    gemm_fused<32, false><<<gB, 128>>>(accB, W3, nullptr, nullptr, nullptr, hw1, nullptr, n, split);
    cudaEventRecord(evG3, 0);

    // ---- layer 3 agg + key (s2; reads hw1), then top-K (main) ----
    cudaStreamWaitEvent(s2, evG3, 0);
    agg32_key<<<(n + 7) / 8, 256, 0, s2>>>(hw1, b3, dinv, rowptr, edges, accA, 0, n, skey, hist1);
    cudaEventRecord(evA3, s2);

    cudaStreamWaitEvent(0, evA3, 0);
    select_topk<<<1, 1024>>>(skey, n, hist1, accA, (float*)d_out);

    for (auto ev : evs) cudaEventDestroy(*ev);
    cudaStreamDestroy(s2);
}

// round 17
// speedup vs baseline: 1.2864x; 1.2864x over previous
#include <cuda_runtime.h>
#include <cuda_bf16.h>

// ---------------------------------------------------------------------------
// MultiLayerGnn: 3-layer GCN (+linear skips) + global_sort_pool top-K
// N=50000, E=800000, F_IN=H=64, C_OUT=32, K=1024
// r8 architecture (serial layer chain, fork prep||gemm1) + deterministic CSR:
// scatter {src,eid} (atomic, any order) then warp-per-node odd-even sort in
// SMEM by eid (canonical original-edge order), finalizing {src, norm}.
// ---------------------------------------------------------------------------

#define NMAX 50000
#define EMAX 800000
#define KTOP 1024
#define MAXDEG 96

static constexpr size_t AL(size_t x) { return (x + 255) & ~size_t(255); }

static constexpr size_t OFF_HW   = 0;
static constexpr size_t OFF_ACCA = AL(OFF_HW   + (size_t)NMAX * 64 * 4);
static constexpr size_t OFF_ACCB = AL(OFF_ACCA + (size_t)NMAX * 64 * 4);
static constexpr size_t OFF_DINV = AL(OFF_ACCB + (size_t)NMAX * 64 * 4);
static constexpr size_t OFF_DEG  = AL(OFF_DINV + (size_t)NMAX * 4);
static constexpr size_t OFF_FILL = AL(OFF_DEG  + (size_t)NMAX * 4);
static constexpr size_t OFF_RP   = AL(OFF_FILL + (size_t)NMAX * 4);
static constexpr size_t OFF_EDG  = AL(OFF_RP   + (size_t)(NMAX + 1) * 4);
static constexpr size_t OFF_SKEY = AL(OFF_EDG  + (size_t)EMAX * 8);
static constexpr size_t OFF_H1   = AL(OFF_SKEY + (size_t)NMAX * 4);
static constexpr size_t OFF_BSUM = AL(OFF_H1   + 4096 * 4);
static constexpr size_t SCRATCH_TOTAL = AL(OFF_BSUM + 256 * 4);

__device__ __align__(256) unsigned char g_scratch[SCRATCH_TOTAL];

// ---------------------------------------------------------------------------
// f32x2 packed-FMA helpers (bit-identical per-lane to fmaf)
// ---------------------------------------------------------------------------

#define FMA2(d, a, b, c) \
    asm("fma.rn.f32x2 %0, %1, %2, %3;" : "=l"(d) : "l"(a), "l"(b), "l"(c))

__device__ __forceinline__ unsigned long long dup2(float x) {
    unsigned long long r; unsigned u = __float_as_uint(x);
    asm("mov.b64 %0, {%1, %2};" : "=l"(r) : "r"(u), "r"(u));
    return r;
}

__device__ __forceinline__ float2 unpk2(unsigned long long v) {
    unsigned lo, hi;
    asm("mov.b64 {%0, %1}, %2;" : "=r"(lo), "=r"(hi) : "l"(v));
    return make_float2(__uint_as_float(lo), __uint_as_float(hi));
}

// ---------------------------------------------------------------------------
// Prep kernels (deg = edge-only count; self-loop via d+1)
// ---------------------------------------------------------------------------

__global__ void init_kernel(int* deg, int* fill, int* hist1, int n) {
    int i = blockIdx.x * blockDim.x + threadIdx.x;
    if (i < n) { deg[i] = 0; fill[i] = 0; }
    if (i < 4096) hist1[i] = 0;
}

// 4 edges per thread for atomic MLP (safe: order canonicalized by sort).
__global__ void deg_kernel(const int* __restrict__ ei, int e,
                           int* __restrict__ deg, int n) {
    int i = (blockIdx.x * blockDim.x + threadIdx.x) * 4;
#pragma unroll
    for (int k = 0; k < 4; k++) {
        int j = i + k;
        if (j < e) {
            unsigned d = (unsigned)ei[e + j];
            if (d < (unsigned)n) atomicAdd(&deg[d], 1);
        }
    }
}

__global__ void scanA(const int* __restrict__ deg, float* __restrict__ dinv,
                      int* __restrict__ bsum, int n) {
    __shared__ int sh[256];
    int t = threadIdx.x;
    int i = blockIdx.x * 256 + t;
    int v = 0;
    if (i < n) {
        int d = deg[i];
        dinv[i] = rsqrtf((float)(d + 1));
        v = d;
    }
    sh[t] = v;
    __syncthreads();
    for (int off = 128; off > 0; off >>= 1) {
        if (t < off) sh[t] += sh[t + off];
        __syncthreads();
    }
    if (t == 0) bsum[blockIdx.x] = sh[0];
}

__global__ void scanC2(const int* __restrict__ deg, const int* __restrict__ bsum,
                       int* __restrict__ rowptr, int nb, int n) {
    __shared__ int sh[256];
    __shared__ int pref;
    int t = threadIdx.x, bid = blockIdx.x;
    sh[t] = (t < bid) ? bsum[t] : 0;     // nb <= 256
    __syncthreads();
    for (int off = 128; off > 0; off >>= 1) {
        if (t < off) sh[t] += sh[t + off];
        __syncthreads();
    }
    if (t == 0) pref = sh[0];
    __syncthreads();
    int i = bid * 256 + t;
    int v = (i < n) ? deg[i] : 0;
    sh[t] = v;
    __syncthreads();
    for (int off = 1; off < 256; off <<= 1) {
        int x = (t >= off) ? sh[t - off] : 0;
        __syncthreads();
        sh[t] += x;
        __syncthreads();
    }
    if (i < n) rowptr[i] = pref + sh[t] - v;
    if (bid == nb - 1 && t == 0) rowptr[n] = pref + bsum[bid];
}

// Records {src, eid}; 4 edges per thread for MLP. Slot order is atomic
// (nondeterministic) — canonicalized by sort_rows_warp.
__global__ void scatter_kernel(const int* __restrict__ ei, int e,
                               const int* __restrict__ rowptr,
                               int* __restrict__ fill,
                               int2* __restrict__ edges, int n) {
    int i = (blockIdx.x * blockDim.x + threadIdx.x) * 4;
#pragma unroll
    for (int k = 0; k < 4; k++) {
        int j = i + k;
        if (j < e) {
            unsigned s = (unsigned)ei[j];
            unsigned d = (unsigned)ei[e + j];
            if (s < (unsigned)n && d < (unsigned)n) {
                int p = atomicAdd(&fill[d], 1);
                edges[rowptr[d] + p] = make_int2((int)s, j);
            }
        }
    }
}

// Warp per node: load row into SMEM, odd-even transposition sort by eid
// (unique -> canonical original-edge order), write back {src, norm} with
// norm = dinv[src]*dinv[node] (single rounding; bit-identical to all
// previous variants). Serial fallback for deg > MAXDEG (never expected).
__global__ void sort_rows_warp(int2* __restrict__ edges,
                               const int* __restrict__ rowptr,
                               const float* __restrict__ dinv, int n) {
    __shared__ int2 sbuf[8][MAXDEG];
    int warp = (blockIdx.x * blockDim.x + threadIdx.x) >> 5;
    int wslot = (threadIdx.x >> 5);
    int lane = threadIdx.x & 31;
    if (warp >= n) return;
    int r0 = rowptr[warp], r1 = rowptr[warp + 1];
    int len = r1 - r0;
    float di = dinv[warp];
    if (len <= MAXDEG) {
        for (int i = lane; i < len; i += 32) sbuf[wslot][i] = edges[r0 + i];
        __syncwarp();
        for (int ph = 0; ph < len; ph++) {
            int start = ph & 1;
#pragma unroll 2
            for (int i = start + 2 * lane; i + 1 < len; i += 64) {
                int2 a = sbuf[wslot][i], b = sbuf[wslot][i + 1];
                if (a.y > b.y) { sbuf[wslot][i] = b; sbuf[wslot][i + 1] = a; }
            }
            __syncwarp();
        }
        for (int i = lane; i < len; i += 32) {
            int s = sbuf[wslot][i].x;
            edges[r0 + i] = make_int2(s, __float_as_int(dinv[s] * di));
        }
    } else {
        if (lane == 0) {
            for (int i = r0 + 1; i < r1; i++) {
                int2 key = edges[i];
                int j = i - 1;
                while (j >= r0 && edges[j].y > key.y) { edges[j + 1] = edges[j]; j--; }
                edges[j + 1] = key;
            }
            for (int i = r0; i < r1; i++) {
                int s = edges[i].x;
                edges[i] = make_int2(s, __float_as_int(dinv[s] * di));
            }
        }
        __syncwarp();
    }
}

// ---------------------------------------------------------------------------
// Fused GEMM via packed f32x2 FMA (r8 verbatim)
// ---------------------------------------------------------------------------

template <int CW, bool SKIP>
__global__ __launch_bounds__(128) void gemm_fused(
    const float* __restrict__ hin,
    const float* __restrict__ W, const float* __restrict__ Wl,
    const float* __restrict__ b, const float* __restrict__ bl,
    float* __restrict__ hw, float* __restrict__ accout, int n) {
    constexpr int HOUT = SKIP ? CW / 2 : CW;
    constexpr int CT = CW / 16;
    constexpr int CT2 = CT / 2;
    __shared__ float As[64][64];   // As[k][row] (transposed)
    __shared__ float Ws[64][CW];

    int tid = threadIdx.x;
    int base = blockIdx.x * 64;

    for (int f = tid; f < 64 * 16; f += 128) {
        int row = f >> 4, c4 = f & 15;
        float4 v = make_float4(0.f, 0.f, 0.f, 0.f);
        int gr = base + row;
        if (gr < n) v = ((const float4*)hin)[(size_t)gr * 16 + c4];
        int k = c4 * 4;
        As[k + 0][row] = v.x;
        As[k + 1][row] = v.y;
        As[k + 2][row] = v.z;
        As[k + 3][row] = v.w;
    }
    for (int f = tid; f < 64 * CW; f += 128) {
        int k = f / CW, j = f % CW;
        float w;
        if (SKIP) w = (j < HOUT) ? W[k * HOUT + j] : Wl[k * HOUT + (j - HOUT)];
        else      w = W[k * CW + j];
        Ws[k][j] = w;
    }
    __syncthreads();

    int tcol = tid & 15, trow = tid >> 4;
    unsigned long long acc2[8][CT2];
#pragma unroll
    for (int i = 0; i < 8; i++)
#pragma unroll
        for (int c = 0; c < CT2; c++) acc2[i][c] = 0ull;

#pragma unroll 4
    for (int k = 0; k < 64; k++) {
        float4 a0 = *(const float4*)&As[k][trow * 8];
        float4 a1 = *(const float4*)&As[k][trow * 8 + 4];
        float a[8] = {a0.x, a0.y, a0.z, a0.w, a1.x, a1.y, a1.z, a1.w};
        unsigned long long w2[CT2];
#pragma unroll
        for (int c = 0; c < CT2; c++)
            w2[c] = *(const unsigned long long*)&Ws[k][tcol * CT + 2 * c];
#pragma unroll
        for (int i = 0; i < 8; i++) {
            unsigned long long ad = dup2(a[i]);
#pragma unroll
            for (int c = 0; c < CT2; c++)
                FMA2(acc2[i][c], ad, w2[c], acc2[i][c]);
        }
    }

#pragma unroll
    for (int i = 0; i < 8; i++) {
        int gr = base + trow * 8 + i;
        if (gr >= n) continue;
#pragma unroll
        for (int c = 0; c < CT2; c++) {
            int col = tcol * CT + 2 * c;
            float2 p = unpk2(acc2[i][c]);
            if (SKIP) {
                if (col < HOUT) {
                    *(float2*)&hw[(size_t)gr * HOUT + col] = p;
                } else {
                    int j = col - HOUT;
                    accout[(size_t)gr * HOUT + j]     = b[j]     + 0.5f * (p.x + bl[j]);
                    accout[(size_t)gr * HOUT + j + 1] = b[j + 1] + 0.5f * (p.y + bl[j + 1]);
                }
            } else {
                *(float2*)&hw[(size_t)gr * CW + col] = p;
            }
        }
    }
}

// ---------------------------------------------------------------------------
// Aggregation: warp per node, {src, norm} records (r11-proven kernels)
// ---------------------------------------------------------------------------

__global__ void agg64(const float* __restrict__ hw, const float* accin,
                      const float* __restrict__ dinv,
                      const int* __restrict__ rowptr,
                      const int2* __restrict__ edges,
                      float* out, int n) {
    int w = (blockIdx.x * blockDim.x + threadIdx.x) >> 5;
    int lane = threadIdx.x & 31;
    if (w >= n) return;
    const float2* hp = (const float2*)hw;
    float di = dinv[w];
    float di2 = di * di;
    float2 s2 = hp[(size_t)w * 32 + lane];
    float ax = s2.x * di2, ay = s2.y * di2;
    int e = rowptr[w], e1 = rowptr[w + 1];
    for (; e + 3 < e1; e += 4) {
        int2 d0 = edges[e],     d1 = edges[e + 1];
        int2 d2 = edges[e + 2], d3 = edges[e + 3];
        float2 v0 = hp[(size_t)d0.x * 32 + lane];
        float2 v1 = hp[(size_t)d1.x * 32 + lane];
        float2 v2 = hp[(size_t)d2.x * 32 + lane];
        float2 v3 = hp[(size_t)d3.x * 32 + lane];
        float n0 = __int_as_float(d0.y), n1 = __int_as_float(d1.y);
        float n2 = __int_as_float(d2.y), n3 = __int_as_float(d3.y);
        ax = fmaf(v0.x, n0, ax); ay = fmaf(v0.y, n0, ay);
        ax = fmaf(v1.x, n1, ax); ay = fmaf(v1.y, n1, ay);
        ax = fmaf(v2.x, n2, ax); ay = fmaf(v2.y, n2, ay);
        ax = fmaf(v3.x, n3, ax); ay = fmaf(v3.y, n3, ay);
    }
    for (; e < e1; e++) {
        int2 d0 = edges[e];
        float2 va = hp[(size_t)d0.x * 32 + lane];
        float na = __int_as_float(d0.y);
        ax = fmaf(va.x, na, ax); ay = fmaf(va.y, na, ay);
    }
    float2 bse = ((const float2*)accin)[(size_t)w * 32 + lane];
    float rx = fmaxf(bse.x + ax, 0.f);
    float ry = fmaxf(bse.y + ay, 0.f);
    ((float2*)out)[(size_t)w * 32 + lane] = make_float2(rx, ry);
}

// Layer-3 agg (32 ch) + fused sort-key + hist1 (lane 31 owns channel 31).
__global__ void agg32_key(const float* __restrict__ hw, const float* __restrict__ bias,
                          const float* __restrict__ dinv,
                          const int* __restrict__ rowptr,
                          const int2* __restrict__ edges,
                          float* __restrict__ out, int n,
                          unsigned* __restrict__ skey, int* __restrict__ hist1) {
    int w = (blockIdx.x * blockDim.x + threadIdx.x) >> 5;
    int lane = threadIdx.x & 31;
    if (w >= n) return;
    float di = dinv[w];
    float di2 = di * di;
    float acc = hw[(size_t)w * 32 + lane] * di2;
    int e = rowptr[w], e1 = rowptr[w + 1];
    for (; e + 3 < e1; e += 4) {
        int2 d0 = edges[e],     d1 = edges[e + 1];
        int2 d2 = edges[e + 2], d3 = edges[e + 3];
        float v0 = hw[(size_t)d0.x * 32 + lane];
        float v1 = hw[(size_t)d1.x * 32 + lane];
        float v2 = hw[(size_t)d2.x * 32 + lane];
        float v3 = hw[(size_t)d3.x * 32 + lane];
        acc = fmaf(v0, __int_as_float(d0.y), acc);
        acc = fmaf(v1, __int_as_float(d1.y), acc);
        acc = fmaf(v2, __int_as_float(d2.y), acc);
        acc = fmaf(v3, __int_as_float(d3.y), acc);
    }
    for (; e < e1; e++) {
        int2 d0 = edges[e];
        acc = fmaf(hw[(size_t)d0.x * 32 + lane], __int_as_float(d0.y), acc);
    }
    float v = acc + bias[lane];
    out[(size_t)w * 32 + lane] = v;
    if (lane == 31) {
        unsigned u = __float_as_uint(v);
        unsigned s = (u & 0x80000000u) ? ~u : (u | 0x80000000u);
        skey[w] = s;
        atomicAdd(&hist1[s >> 20], 1);
    }
}

// ---------------------------------------------------------------------------
// Merged top-K finisher (r8 verbatim)
// ---------------------------------------------------------------------------

__device__ __forceinline__ void findbin_warp(const int* __restrict__ hist,
                                             int base, int need,
                                             int* outB, int* outCum) {
    int lane = threadIdx.x & 31;
    int hi = 4095 - 128 * lane;
    int s = 0;
    for (int k = 0; k < 128; k++) s += hist[hi - k];
    int incl = s;
#pragma unroll
    for (int off = 1; off < 32; off <<= 1) {
        int x = __shfl_up_sync(0xFFFFFFFFu, incl, off);
        if (lane >= off) incl += x;
    }
    int excl = incl - s;
    if (base + excl < need && base + incl >= need) {
        int c = base + excl;
        int b = hi;
        while (c + hist[b] < need) { c += hist[b]; b--; }
        *outB = b;
        *outCum = c;
    }
}

__global__ __launch_bounds__(1024) void select_topk(
    const unsigned* __restrict__ skey, int n,
    const int* __restrict__ hist1,
    const float* __restrict__ h3, float* __restrict__ out) {
    __shared__ unsigned long long sd[4096];
    __shared__ int B1, C1, B2, C2, scnt;
    __shared__ unsigned Tsh;
    int* hist2 = (int*)sd;
    int tid = threadIdx.x;

    if (tid == 0) scnt = 0;
    for (int i = tid; i < 4096; i += 1024) hist2[i] = 0;
    __syncthreads();

    if (tid < 32) findbin_warp(hist1, 0, KTOP, &B1, &C1);
    __syncthreads();
    int b1 = B1, c1 = C1;

    for (int i = tid; i < n; i += 1024) {
        unsigned s = skey[i];
        if ((int)(s >> 20) == b1) atomicAdd(&hist2[(s >> 8) & 0xFFF], 1);
    }
    __syncthreads();

    if (tid < 32) findbin_warp(hist2, c1, KTOP, &B2, &C2);
    __syncthreads();
    if (tid == 0) Tsh = (((unsigned)b1) << 20) | (((unsigned)B2) << 8);
    __syncthreads();
    unsigned T = Tsh;
    __syncthreads();

    for (int i = tid; i < n; i += 1024) {
        unsigned s = skey[i];
        if (s >= T) {
            int p = atomicAdd(&scnt, 1);
            if (p < 4096)
                sd[p] = (((unsigned long long)s) << 32) |
                        (unsigned long long)(0xFFFFFFFFu - (unsigned)i);
        }
    }
    __syncthreads();

    int C = scnt; if (C > 4096) C = 4096;
    int S = 1024; while (S < C) S <<= 1;
    for (int i = tid; i < S; i += 1024) if (i >= C) sd[i] = 0ull;
    __syncthreads();
    for (int k = 2; k <= S; k <<= 1) {
        for (int j = k >> 1; j > 0; j >>= 1) {
            for (int t = tid; t < S; t += 1024) {
                int ixj = t ^ j;
                if (ixj > t) {
                    bool up = ((t & k) == 0);
                    unsigned long long A = sd[t], Bv = sd[ixj];
                    bool sw = up ? (A < Bv) : (A > Bv);
                    if (sw) { sd[t] = Bv; sd[ixj] = A; }
                }
            }
            __syncthreads();
        }
    }
    for (int t = tid; t < KTOP * 32; t += 1024) {
        int r = t >> 5, c = t & 31;
        unsigned idx = 0xFFFFFFFFu - (unsigned)(sd[r] & 0xFFFFFFFFull);
        out[t] = h3[(size_t)idx * 32 + c];
    }
}

// ---------------------------------------------------------------------------
// Launch (r8 flow: prep on s2 overlapping GEMM layer 1; serial layer chain)
// ---------------------------------------------------------------------------

extern "C" void kernel_launch(void* const* d_in, const int* in_sizes, int n_in,
                              void* d_out, int out_size) {
    const float* x   = (const float*)d_in[0];
    const float* W1  = (const float*)d_in[1];
    const float* b1  = (const float*)d_in[2];
    const float* Wl1 = (const float*)d_in[3];
    const float* bl1 = (const float*)d_in[4];
    const float* W2  = (const float*)d_in[5];
    const float* b2  = (const float*)d_in[6];
    const float* Wl2 = (const float*)d_in[7];
    const float* bl2 = (const float*)d_in[8];
    const float* W3  = (const float*)d_in[9];
    const float* b3  = (const float*)d_in[10];
    const int*   ei  = (const int*)d_in[11];

    int n = in_sizes[0] / 64;
    int e = in_sizes[11] / 2;

    unsigned char* base = nullptr;
    cudaGetSymbolAddress((void**)&base, g_scratch);

    float* hw      = (float*)(base + OFF_HW);
    float* accA    = (float*)(base + OFF_ACCA);
    float* accB    = (float*)(base + OFF_ACCB);
    float* dinv    = (float*)(base + OFF_DINV);
    int*   deg     = (int*)(base + OFF_DEG);
    int*   fill    = (int*)(base + OFF_FILL);
    int*   rowptr  = (int*)(base + OFF_RP);
    int2*  edges   = (int2*)(base + OFF_EDG);
    unsigned* skey = (unsigned*)(base + OFF_SKEY);
    int*   hist1   = (int*)(base + OFF_H1);
    int*   bsum    = (int*)(base + OFF_BSUM);

    int ninit = (n > 4096) ? n : 4096;
    int nb = (n + 255) / 256;
    int gblocks = (n + 63) / 64;
    int ablocks = (n + 7) / 8;

    cudaStream_t s2;
    cudaStreamCreate(&s2);
    cudaEvent_t evFork, evJoin;
    cudaEventCreateWithFlags(&evFork, cudaEventDisableTiming);
    cudaEventCreateWithFlags(&evJoin, cudaEventDisableTiming);

    cudaEventRecord(evFork, 0);
    cudaStreamWaitEvent(s2, evFork, 0);

    // prep branch (s2)
    init_kernel<<<(ninit + 255) / 256, 256, 0, s2>>>(deg, fill, hist1, n);
    deg_kernel<<<(e + 1023) / 1024, 256, 0, s2>>>(ei, e, deg, n);
    scanA<<<nb, 256, 0, s2>>>(deg, dinv, bsum, n);
    scanC2<<<nb, 256, 0, s2>>>(deg, bsum, rowptr, nb, n);
    scatter_kernel<<<(e + 1023) / 1024, 256, 0, s2>>>(ei, e, rowptr, fill, edges, n);
    sort_rows_warp<<<ablocks, 256, 0, s2>>>(edges, rowptr, dinv, n);
    cudaEventRecord(evJoin, s2);

    // main stream: GEMM layer 1 (independent of CSR)
    gemm_fused<128, true><<<gblocks, 128>>>(x, W1, Wl1, b1, bl1, hw, accA, n);

    // join
    cudaStreamWaitEvent(0, evJoin, 0);

    agg64<<<ablocks, 256>>>(hw, accA, dinv, rowptr, edges, accA, n);
    // Layer 2
    gemm_fused<128, true><<<gblocks, 128>>>(accA, W2, Wl2, b2, bl2, hw, accB, n);
    agg64<<<ablocks, 256>>>(hw, accB, dinv, rowptr, edges, accB, n);
    // Layer 3 (no skip, 32 channels) + fused key/hist
    gemm_fused<32, false><<<gblocks, 128>>>(accB, W3, nullptr, nullptr, nullptr, hw, nullptr, n);
    agg32_key<<<ablocks, 256>>>(hw, b3, dinv, rowptr, edges, accA, n, skey, hist1);

    // Merged top-K finisher
    select_topk<<<1, 1024>>>(skey, n, hist1, accA, (float*)d_out);

    cudaEventDestroy(evFork);
    cudaEventDestroy(evJoin);
    cudaStreamDestroy(s2);
}